// round 2
// baseline (speedup 1.0000x reference)
#include <cuda_runtime.h>
#include <cstdint>

typedef unsigned long long ull;

// ---------------- problem constants ----------------
#define TE      64      // edges per block
#define NT      256     // threads per block
#define XS      260     // smem stride of X rows (256 + pad, multiple of 4 for float4)
#define HS      132     // smem stride of H rows (128 + pad, multiple of 4)
#define MSGIN   256
#define HID     128
#define XDIM    96

// ---------------- f32x2 helpers ----------------
__device__ __forceinline__ ull pk2(float a, float b) {
    ull r; asm("mov.b64 %0, {%1,%2};" : "=l"(r) : "f"(a), "f"(b)); return r;
}
__device__ __forceinline__ void upk2(ull v, float& a, float& b) {
    asm("mov.b64 {%0,%1}, %2;" : "=f"(a), "=f"(b) : "l"(v));
}
__device__ __forceinline__ ull ffma2(ull a, ull b, ull c) {
    ull d; asm("fma.rn.f32x2 %0, %1, %2, %3;" : "=l"(d) : "l"(a), "l"(b), "l"(c)); return d;
}
__device__ __forceinline__ void red4(float* p, float4 v) {
    asm volatile("red.global.add.v4.f32 [%0], {%1,%2,%3,%4};"
                 :: "l"(p), "f"(v.x), "f"(v.y), "f"(v.z), "f"(v.w) : "memory");
}

__global__ __launch_bounds__(NT, 2)
void eq_edge_kernel(const float* __restrict__ xs,   // (N,32)
                    const float* __restrict__ xr,   // (N,8,8)
                    const int*   __restrict__ ei,   // (2,E)
                    const float* __restrict__ dist, // (E,64)
                    const float* __restrict__ rot,  // (E,4,2,2)
                    const float* __restrict__ W1,   // (256,128)
                    const float* __restrict__ b1,   // (128)
                    const float* __restrict__ W2,   // (128,96)
                    const float* __restrict__ b2,   // (96)
                    float* __restrict__ outS,       // (N,32)
                    float* __restrict__ outR,       // (N,64)
                    int E)
{
    extern __shared__ float sm[];
    float* sX  = sm;                         // TE*XS floats
    float* sW  = sm + TE * XS;               // 4096 floats (weight tile)
    int*   sDst = (int*)(sm + TE * XS + 4096); // TE ints
    float* sH  = sX;                         // overlays X, stride HS
    float* sM  = sX + TE * HS;               // messages, 64x96, after H

    const int tid  = threadIdx.x;
    const int base = blockIdx.x * TE;

    // ================= Phase A: build X rows =================
    {
        const int eL = tid >> 2;
        const int s  = tid & 3;
        const int e  = base + eL;
        if (e < E) {
            const int src = ei[e];
            const int dst = ei[E + e];
            if (s == 0) sDst[eL] = dst;
            float* Xr = sX + eL * XS;

            // x_scalar parts (dst first, then src)
            {
                const float4* ps = (const float4*)(xs + (size_t)dst * 32 + s * 8);
                *(float4*)(Xr + s * 8)     = ps[0];
                *(float4*)(Xr + s * 8 + 4) = ps[1];
                const float4* pr = (const float4*)(xs + (size_t)src * 32 + s * 8);
                *(float4*)(Xr + 96 + s * 8)     = pr[0];
                *(float4*)(Xr + 96 + s * 8 + 4) = pr[1];
            }
            // distance embedding
            {
                const float4* pd = (const float4*)(dist + (size_t)e * 64 + s * 16);
                float4* od = (float4*)(Xr + 192 + s * 16);
                #pragma unroll
                for (int i = 0; i < 4; i++) od[i] = pd[i];
            }
            // rotation matrices for this edge: rk[k] = (R[k,0,0],R[k,0,1],R[k,1,0],R[k,1,1])
            float4 rk[4];
            #pragma unroll
            for (int k = 0; k < 4; k++)
                rk[k] = *(const float4*)(rot + (size_t)e * 16 + k * 4);

            // rotated reps: this thread does reps 2s, 2s+1 for both nodes
            #pragma unroll
            for (int jj = 0; jj < 2; jj++) {
                const int j = 2 * s + jj;
                // dst node (inverse rotation): out[l] = x0*R[k,l,0] + x1*R[k,l,1]
                {
                    const float4* pv = (const float4*)(xr + (size_t)dst * 64 + j * 8);
                    float4 a = pv[0], b = pv[1];
                    float xv[8] = {a.x,a.y,a.z,a.w, b.x,b.y,b.z,b.w};
                    float* o = Xr + 32 + j * 8;
                    #pragma unroll
                    for (int k = 0; k < 4; k++) {
                        float x0 = xv[2*k], x1 = xv[2*k+1];
                        o[2*k]   = x0 * rk[k].x + x1 * rk[k].y;
                        o[2*k+1] = x0 * rk[k].z + x1 * rk[k].w;
                    }
                }
                // src node
                {
                    const float4* pv = (const float4*)(xr + (size_t)src * 64 + j * 8);
                    float4 a = pv[0], b = pv[1];
                    float xv[8] = {a.x,a.y,a.z,a.w, b.x,b.y,b.z,b.w};
                    float* o = Xr + 128 + j * 8;
                    #pragma unroll
                    for (int k = 0; k < 4; k++) {
                        float x0 = xv[2*k], x1 = xv[2*k+1];
                        o[2*k]   = x0 * rk[k].x + x1 * rk[k].y;
                        o[2*k+1] = x0 * rk[k].z + x1 * rk[k].w;
                    }
                }
            }
        }
    }
    // (first weight-tile sync below doubles as the phase-A barrier)

    // ================= GEMM1: H = silu(X @ W1 + b1) =================
    const int cg = tid & 31;   // col group: cols cg*4 .. cg*4+3
    const int eg = tid >> 5;   // edge group: edges eg*8 .. eg*8+7
    ull acc[8][2] = {};        // 8 edges x 2 f32x2 col-pairs

    for (int kt = 0; kt < MSGIN; kt += 32) {
        // stage W1[kt:kt+32, :] into smem (4096 floats)
        {
            const float4* g = (const float4*)(W1 + (size_t)kt * HID);
            float4* sp = (float4*)sW;
            #pragma unroll
            for (int i = 0; i < 4; i++) sp[tid + i * NT] = g[tid + i * NT];
        }
        __syncthreads();
        #pragma unroll 4
        for (int kk = 0; kk < 32; kk++) {
            float4 w = *(const float4*)(sW + kk * HID + cg * 4);
            ull w01 = pk2(w.x, w.y), w23 = pk2(w.z, w.w);
            #pragma unroll
            for (int i = 0; i < 8; i++) {
                float x = sX[(eg * 8 + i) * XS + kt + kk];
                ull xx = pk2(x, x);
                acc[i][0] = ffma2(xx, w01, acc[i][0]);
                acc[i][1] = ffma2(xx, w23, acc[i][1]);
            }
        }
        __syncthreads();
    }

    // bias + silu, store H (overlays now-dead X)
    {
        float4 bb = *(const float4*)(b1 + cg * 4);
        #pragma unroll
        for (int i = 0; i < 8; i++) {
            float a0, a1, a2, a3;
            upk2(acc[i][0], a0, a1);
            upk2(acc[i][1], a2, a3);
            a0 += bb.x; a1 += bb.y; a2 += bb.z; a3 += bb.w;
            a0 = a0 / (1.f + __expf(-a0));
            a1 = a1 / (1.f + __expf(-a1));
            a2 = a2 / (1.f + __expf(-a2));
            a3 = a3 / (1.f + __expf(-a3));
            *(float4*)(sH + (eg * 8 + i) * HS + cg * 4) = make_float4(a0, a1, a2, a3);
        }
    }

    // ================= GEMM2: OUT = H @ W2 + b2 =================
    const int sub = tid & 15;  // cols sub*6 .. sub*6+5 (3 even-aligned pairs)
    const int e0  = tid >> 4;  // edges e0, e0+16, e0+32, e0+48
    ull acc2[4][3] = {};

    for (int kt = 0; kt < HID; kt += 32) {
        // stage W2[kt:kt+32, :] (3072 floats)
        {
            const float4* g = (const float4*)(W2 + (size_t)kt * XDIM);
            float4* sp = (float4*)sW;
            #pragma unroll
            for (int i = 0; i < 3; i++) sp[tid + i * NT] = g[tid + i * NT];
        }
        __syncthreads();
        #pragma unroll 4
        for (int kk = 0; kk < 32; kk++) {
            const float* wr = sW + kk * XDIM + sub * 6;
            ull w01 = *(const ull*)(wr);
            ull w23 = *(const ull*)(wr + 2);
            ull w45 = *(const ull*)(wr + 4);
            #pragma unroll
            for (int t = 0; t < 4; t++) {
                float h = sH[(e0 + t * 16) * HS + kt + kk];
                ull hh = pk2(h, h);
                acc2[t][0] = ffma2(hh, w01, acc2[t][0]);
                acc2[t][1] = ffma2(hh, w23, acc2[t][1]);
                acc2[t][2] = ffma2(hh, w45, acc2[t][2]);
            }
        }
        __syncthreads();
    }

    // bias + forward rotation, store messages into sM
    {
        const int cb = sub * 6;
        float b2v[6];
        #pragma unroll
        for (int p = 0; p < 6; p++) b2v[p] = b2[cb + p];

        #pragma unroll
        for (int t = 0; t < 4; t++) {
            const int eL = e0 + t * 16;
            const int e  = base + eL;
            float mv[6];
            upk2(acc2[t][0], mv[0], mv[1]);
            upk2(acc2[t][1], mv[2], mv[3]);
            upk2(acc2[t][2], mv[4], mv[5]);
            #pragma unroll
            for (int p = 0; p < 6; p++) mv[p] += b2v[p];

            float* Mr = sM + eL * XDIM;
            #pragma unroll
            for (int p = 0; p < 3; p++) {
                const int c = cb + 2 * p;
                float u0 = mv[2 * p], u1 = mv[2 * p + 1];
                if (c < 32) {             // scalar message
                    Mr[c]     = u0;
                    Mr[c + 1] = u1;
                } else {                  // rot message: out[l] = m0*R[k,0,l] + m1*R[k,1,l]
                    const int cc = c - 32;
                    const int kidx = (cc >> 1) & 3;
                    float4 r = (e < E) ? *(const float4*)(rot + (size_t)e * 16 + kidx * 4)
                                       : make_float4(0.f, 0.f, 0.f, 0.f);
                    Mr[c]     = u0 * r.x + u1 * r.z;
                    Mr[c + 1] = u0 * r.y + u1 * r.w;
                }
            }
        }
    }
    __syncthreads();

    // ================= Scatter: vector atomic add into outputs =================
    #pragma unroll
    for (int it = 0; it < 6; it++) {
        const int q  = tid + it * NT;        // 0 .. 1535 = 64 edges * 24 float4
        const int eL = q / 24;
        const int c4 = q % 24;
        const int e  = base + eL;
        if (e < E) {
            const int n = sDst[eL];
            float4 v = *(const float4*)(sM + eL * XDIM + c4 * 4);
            float* p = (c4 < 8) ? (outS + (size_t)n * 32 + c4 * 4)
                                : (outR + (size_t)n * 64 + (size_t)(c4 - 8) * 4);
            red4(p, v);
        }
    }
}

// ---------------- launch ----------------
extern "C" void kernel_launch(void* const* d_in, const int* in_sizes, int n_in,
                              void* d_out, int out_size)
{
    const float* xs   = (const float*)d_in[0];
    const float* xr   = (const float*)d_in[1];
    const int*   ei   = (const int*)  d_in[2];
    const float* dist = (const float*)d_in[3];
    const float* rot  = (const float*)d_in[4];
    const float* W1   = (const float*)d_in[5];
    const float* b1   = (const float*)d_in[6];
    const float* W2   = (const float*)d_in[7];
    const float* b2   = (const float*)d_in[8];

    const int N = in_sizes[0] / 32;
    const int E = in_sizes[2] / 2;

    float* outS = (float*)d_out;
    float* outR = outS + (size_t)N * 32;

    cudaMemsetAsync(d_out, 0, (size_t)out_size * sizeof(float), 0);

    const int smem_bytes = (TE * XS + 4096) * (int)sizeof(float) + TE * (int)sizeof(int);
    cudaFuncSetAttribute(eq_edge_kernel, cudaFuncAttributeMaxDynamicSharedMemorySize, smem_bytes);

    const int grid = (E + TE - 1) / TE;
    eq_edge_kernel<<<grid, NT, smem_bytes>>>(xs, xr, ei, dist, rot, W1, b1, W2, b2,
                                             outS, outR, E);
}

// round 3
// speedup vs baseline: 1.0002x; 1.0002x over previous
#include <cuda_runtime.h>
#include <cstdint>

typedef unsigned long long ull;

// ---------------- problem constants ----------------
#define TE      64      // edges per block
#define NT      256     // threads per block
#define XS      260     // smem stride of X rows (256 + pad, multiple of 4 for float4)
#define HS      132     // smem stride of H rows (128 + pad, multiple of 4)
#define MSGIN   256
#define HID     128
#define XDIM    96

// ---------------- f32x2 helpers ----------------
__device__ __forceinline__ ull pk2(float a, float b) {
    ull r; asm("mov.b64 %0, {%1,%2};" : "=l"(r) : "f"(a), "f"(b)); return r;
}
__device__ __forceinline__ void upk2(ull v, float& a, float& b) {
    asm("mov.b64 {%0,%1}, %2;" : "=f"(a), "=f"(b) : "l"(v));
}
__device__ __forceinline__ ull ffma2(ull a, ull b, ull c) {
    ull d; asm("fma.rn.f32x2 %0, %1, %2, %3;" : "=l"(d) : "l"(a), "l"(b), "l"(c)); return d;
}
__device__ __forceinline__ void red4(float* p, float4 v) {
    asm volatile("red.global.add.v4.f32 [%0], {%1,%2,%3,%4};"
                 :: "l"(p), "f"(v.x), "f"(v.y), "f"(v.z), "f"(v.w) : "memory");
}

__global__ __launch_bounds__(NT, 2)
void eq_edge_kernel(const float* __restrict__ xs,   // (N,32)
                    const float* __restrict__ xr,   // (N,8,8)
                    const int*   __restrict__ ei,   // (2,E)
                    const float* __restrict__ dist, // (E,64)
                    const float* __restrict__ rot,  // (E,4,2,2)
                    const float* __restrict__ W1,   // (256,128)
                    const float* __restrict__ b1,   // (128)
                    const float* __restrict__ W2,   // (128,96)
                    const float* __restrict__ b2,   // (96)
                    float* __restrict__ outS,       // (N,32)
                    float* __restrict__ outR,       // (N,64)
                    int E)
{
    extern __shared__ float sm[];
    float* sX  = sm;                         // TE*XS floats
    float* sW  = sm + TE * XS;               // 4096 floats (weight tile)
    int*   sDst = (int*)(sm + TE * XS + 4096); // TE ints
    float* sH  = sX;                         // overlays X, stride HS
    float* sM  = sX + TE * HS;               // messages, 64x96, after H

    const int tid  = threadIdx.x;
    const int base = blockIdx.x * TE;

    // ================= Phase A: build X rows =================
    {
        const int eL = tid >> 2;
        const int s  = tid & 3;
        const int e  = base + eL;
        if (e < E) {
            const int src = ei[e];
            const int dst = ei[E + e];
            if (s == 0) sDst[eL] = dst;
            float* Xr = sX + eL * XS;

            // x_scalar parts (dst first, then src)
            {
                const float4* ps = (const float4*)(xs + (size_t)dst * 32 + s * 8);
                *(float4*)(Xr + s * 8)     = ps[0];
                *(float4*)(Xr + s * 8 + 4) = ps[1];
                const float4* pr = (const float4*)(xs + (size_t)src * 32 + s * 8);
                *(float4*)(Xr + 96 + s * 8)     = pr[0];
                *(float4*)(Xr + 96 + s * 8 + 4) = pr[1];
            }
            // distance embedding
            {
                const float4* pd = (const float4*)(dist + (size_t)e * 64 + s * 16);
                float4* od = (float4*)(Xr + 192 + s * 16);
                #pragma unroll
                for (int i = 0; i < 4; i++) od[i] = pd[i];
            }
            // rotation matrices for this edge: rk[k] = (R[k,0,0],R[k,0,1],R[k,1,0],R[k,1,1])
            float4 rk[4];
            #pragma unroll
            for (int k = 0; k < 4; k++)
                rk[k] = *(const float4*)(rot + (size_t)e * 16 + k * 4);

            // rotated reps: this thread does reps 2s, 2s+1 for both nodes
            #pragma unroll
            for (int jj = 0; jj < 2; jj++) {
                const int j = 2 * s + jj;
                // dst node (inverse rotation): out[l] = x0*R[k,l,0] + x1*R[k,l,1]
                {
                    const float4* pv = (const float4*)(xr + (size_t)dst * 64 + j * 8);
                    float4 a = pv[0], b = pv[1];
                    float xv[8] = {a.x,a.y,a.z,a.w, b.x,b.y,b.z,b.w};
                    float* o = Xr + 32 + j * 8;
                    #pragma unroll
                    for (int k = 0; k < 4; k++) {
                        float x0 = xv[2*k], x1 = xv[2*k+1];
                        o[2*k]   = x0 * rk[k].x + x1 * rk[k].y;
                        o[2*k+1] = x0 * rk[k].z + x1 * rk[k].w;
                    }
                }
                // src node
                {
                    const float4* pv = (const float4*)(xr + (size_t)src * 64 + j * 8);
                    float4 a = pv[0], b = pv[1];
                    float xv[8] = {a.x,a.y,a.z,a.w, b.x,b.y,b.z,b.w};
                    float* o = Xr + 128 + j * 8;
                    #pragma unroll
                    for (int k = 0; k < 4; k++) {
                        float x0 = xv[2*k], x1 = xv[2*k+1];
                        o[2*k]   = x0 * rk[k].x + x1 * rk[k].y;
                        o[2*k+1] = x0 * rk[k].z + x1 * rk[k].w;
                    }
                }
            }
        }
    }
    // (first weight-tile sync below doubles as the phase-A barrier)

    // ================= GEMM1: H = silu(X @ W1 + b1) =================
    const int cg = tid & 31;   // col group: cols cg*4 .. cg*4+3
    const int eg = tid >> 5;   // edge group: edges eg*8 .. eg*8+7
    ull acc[8][2] = {};        // 8 edges x 2 f32x2 col-pairs

    for (int kt = 0; kt < MSGIN; kt += 32) {
        // stage W1[kt:kt+32, :] into smem (4096 floats)
        {
            const float4* g = (const float4*)(W1 + (size_t)kt * HID);
            float4* sp = (float4*)sW;
            #pragma unroll
            for (int i = 0; i < 4; i++) sp[tid + i * NT] = g[tid + i * NT];
        }
        __syncthreads();
        #pragma unroll 4
        for (int kk = 0; kk < 32; kk++) {
            float4 w = *(const float4*)(sW + kk * HID + cg * 4);
            ull w01 = pk2(w.x, w.y), w23 = pk2(w.z, w.w);
            #pragma unroll
            for (int i = 0; i < 8; i++) {
                float x = sX[(eg * 8 + i) * XS + kt + kk];
                ull xx = pk2(x, x);
                acc[i][0] = ffma2(xx, w01, acc[i][0]);
                acc[i][1] = ffma2(xx, w23, acc[i][1]);
            }
        }
        __syncthreads();
    }

    // bias + silu, store H (overlays now-dead X)
    {
        float4 bb = *(const float4*)(b1 + cg * 4);
        #pragma unroll
        for (int i = 0; i < 8; i++) {
            float a0, a1, a2, a3;
            upk2(acc[i][0], a0, a1);
            upk2(acc[i][1], a2, a3);
            a0 += bb.x; a1 += bb.y; a2 += bb.z; a3 += bb.w;
            a0 = a0 / (1.f + __expf(-a0));
            a1 = a1 / (1.f + __expf(-a1));
            a2 = a2 / (1.f + __expf(-a2));
            a3 = a3 / (1.f + __expf(-a3));
            *(float4*)(sH + (eg * 8 + i) * HS + cg * 4) = make_float4(a0, a1, a2, a3);
        }
    }

    // ================= GEMM2: OUT = H @ W2 + b2 =================
    const int sub = tid & 15;  // cols sub*6 .. sub*6+5 (3 even-aligned pairs)
    const int e0  = tid >> 4;  // edges e0, e0+16, e0+32, e0+48
    ull acc2[4][3] = {};

    for (int kt = 0; kt < HID; kt += 32) {
        // stage W2[kt:kt+32, :] (3072 floats)
        {
            const float4* g = (const float4*)(W2 + (size_t)kt * XDIM);
            float4* sp = (float4*)sW;
            #pragma unroll
            for (int i = 0; i < 3; i++) sp[tid + i * NT] = g[tid + i * NT];
        }
        __syncthreads();
        #pragma unroll 4
        for (int kk = 0; kk < 32; kk++) {
            const float* wr = sW + kk * XDIM + sub * 6;
            ull w01 = *(const ull*)(wr);
            ull w23 = *(const ull*)(wr + 2);
            ull w45 = *(const ull*)(wr + 4);
            #pragma unroll
            for (int t = 0; t < 4; t++) {
                float h = sH[(e0 + t * 16) * HS + kt + kk];
                ull hh = pk2(h, h);
                acc2[t][0] = ffma2(hh, w01, acc2[t][0]);
                acc2[t][1] = ffma2(hh, w23, acc2[t][1]);
                acc2[t][2] = ffma2(hh, w45, acc2[t][2]);
            }
        }
        __syncthreads();
    }

    // bias + forward rotation, store messages into sM
    {
        const int cb = sub * 6;
        float b2v[6];
        #pragma unroll
        for (int p = 0; p < 6; p++) b2v[p] = b2[cb + p];

        #pragma unroll
        for (int t = 0; t < 4; t++) {
            const int eL = e0 + t * 16;
            const int e  = base + eL;
            float mv[6];
            upk2(acc2[t][0], mv[0], mv[1]);
            upk2(acc2[t][1], mv[2], mv[3]);
            upk2(acc2[t][2], mv[4], mv[5]);
            #pragma unroll
            for (int p = 0; p < 6; p++) mv[p] += b2v[p];

            float* Mr = sM + eL * XDIM;
            #pragma unroll
            for (int p = 0; p < 3; p++) {
                const int c = cb + 2 * p;
                float u0 = mv[2 * p], u1 = mv[2 * p + 1];
                if (c < 32) {             // scalar message
                    Mr[c]     = u0;
                    Mr[c + 1] = u1;
                } else {                  // rot message: out[l] = m0*R[k,0,l] + m1*R[k,1,l]
                    const int cc = c - 32;
                    const int kidx = (cc >> 1) & 3;
                    float4 r = (e < E) ? *(const float4*)(rot + (size_t)e * 16 + kidx * 4)
                                       : make_float4(0.f, 0.f, 0.f, 0.f);
                    Mr[c]     = u0 * r.x + u1 * r.z;
                    Mr[c + 1] = u0 * r.y + u1 * r.w;
                }
            }
        }
    }
    __syncthreads();

    // ================= Scatter: vector atomic add into outputs =================
    #pragma unroll
    for (int it = 0; it < 6; it++) {
        const int q  = tid + it * NT;        // 0 .. 1535 = 64 edges * 24 float4
        const int eL = q / 24;
        const int c4 = q % 24;
        const int e  = base + eL;
        if (e < E) {
            const int n = sDst[eL];
            float4 v = *(const float4*)(sM + eL * XDIM + c4 * 4);
            float* p = (c4 < 8) ? (outS + (size_t)n * 32 + c4 * 4)
                                : (outR + (size_t)n * 64 + (size_t)(c4 - 8) * 4);
            red4(p, v);
        }
    }
}

// ---------------- launch ----------------
extern "C" void kernel_launch(void* const* d_in, const int* in_sizes, int n_in,
                              void* d_out, int out_size)
{
    const float* xs   = (const float*)d_in[0];
    const float* xr   = (const float*)d_in[1];
    const int*   ei   = (const int*)  d_in[2];
    const float* dist = (const float*)d_in[3];
    const float* rot  = (const float*)d_in[4];
    const float* W1   = (const float*)d_in[5];
    const float* b1   = (const float*)d_in[6];
    const float* W2   = (const float*)d_in[7];
    const float* b2   = (const float*)d_in[8];

    const int N = in_sizes[0] / 32;
    const int E = in_sizes[2] / 2;

    float* outS = (float*)d_out;
    float* outR = outS + (size_t)N * 32;

    cudaMemsetAsync(d_out, 0, (size_t)out_size * sizeof(float), 0);

    const int smem_bytes = (TE * XS + 4096) * (int)sizeof(float) + TE * (int)sizeof(int);
    cudaFuncSetAttribute(eq_edge_kernel, cudaFuncAttributeMaxDynamicSharedMemorySize, smem_bytes);

    const int grid = (E + TE - 1) / TE;
    eq_edge_kernel<<<grid, NT, smem_bytes>>>(xs, xr, ei, dist, rot, W1, b1, W2, b2,
                                             outS, outR, E);
}

// round 5
// speedup vs baseline: 2.2305x; 2.2300x over previous
#include <cuda_runtime.h>
#include <cuda_fp16.h>
#include <cstdint>

#define NTHR  512
#define ET    128
#define XSTR  264     // halves
#define W1STR 136
#define W2STR 96
#define HSTR  136
// byte offsets in dynamic smem
#define B_XH  0
#define B_XL  67584
#define B_W1  135168
#define B_W2  204800
#define B_DST 229376
#define SMEMB 229888
#define B_HH  0
#define B_HL  34816

__device__ __forceinline__ uint32_t s2u(const void* p) {
    uint32_t a; asm("{ .reg .u64 t; cvta.to.shared.u64 t, %1; cvt.u32.u64 %0, t; }" : "=r"(a) : "l"(p)); return a;
}
__device__ __forceinline__ void ldsm4(uint32_t a, uint32_t& r0, uint32_t& r1, uint32_t& r2, uint32_t& r3) {
    asm volatile("ldmatrix.sync.aligned.m8n8.x4.shared.b16 {%0,%1,%2,%3}, [%4];"
                 : "=r"(r0), "=r"(r1), "=r"(r2), "=r"(r3) : "r"(a));
}
__device__ __forceinline__ void ldsm4t(uint32_t a, uint32_t& r0, uint32_t& r1, uint32_t& r2, uint32_t& r3) {
    asm volatile("ldmatrix.sync.aligned.m8n8.x4.trans.shared.b16 {%0,%1,%2,%3}, [%4];"
                 : "=r"(r0), "=r"(r1), "=r"(r2), "=r"(r3) : "r"(a));
}
__device__ __forceinline__ void ldsm2t(uint32_t a, uint32_t& r0, uint32_t& r1) {
    asm volatile("ldmatrix.sync.aligned.m8n8.x2.trans.shared.b16 {%0,%1}, [%2];"
                 : "=r"(r0), "=r"(r1) : "r"(a));
}
__device__ __forceinline__ void mma16816(float* c, const uint32_t* a, const uint32_t* b) {
    asm volatile("mma.sync.aligned.m16n8k16.row.col.f32.f16.f16.f32 "
                 "{%0,%1,%2,%3}, {%4,%5,%6,%7}, {%8,%9}, {%0,%1,%2,%3};"
                 : "+f"(c[0]), "+f"(c[1]), "+f"(c[2]), "+f"(c[3])
                 : "r"(a[0]), "r"(a[1]), "r"(a[2]), "r"(a[3]), "r"(b[0]), "r"(b[1]));
}
__device__ __forceinline__ void red2(float* p, float a, float b) {
    asm volatile("red.global.add.v2.f32 [%0], {%1,%2};" :: "l"(p), "f"(a), "f"(b) : "memory");
}
// write 8 fp32 -> fp16 hi + fp16 residual lo at half-index idx (idx even)
__device__ __forceinline__ void wr8(__half* ph, __half* pl, int idx, const float* v) {
    #pragma unroll
    for (int q = 0; q < 4; q++) {
        __half h0 = __float2half_rn(v[2*q]),   h1 = __float2half_rn(v[2*q+1]);
        __half l0 = __float2half_rn(v[2*q]   - __half2float(h0));
        __half l1 = __float2half_rn(v[2*q+1] - __half2float(h1));
        *(uint32_t*)(ph + idx + 2*q) = (uint32_t)__half_as_ushort(h0) | ((uint32_t)__half_as_ushort(h1) << 16);
        *(uint32_t*)(pl + idx + 2*q) = (uint32_t)__half_as_ushort(l0) | ((uint32_t)__half_as_ushort(l1) << 16);
    }
}
// inverse-rotate one rep (8 values) with rk
__device__ __forceinline__ void rot8(const float* p, const float4* rk, float* o) {
    #pragma unroll
    for (int k = 0; k < 4; k++) {
        float x0 = p[2*k], x1 = p[2*k+1];
        o[2*k]   = x0 * rk[k].x + x1 * rk[k].y;
        o[2*k+1] = x0 * rk[k].z + x1 * rk[k].w;
    }
}

__global__ __launch_bounds__(NTHR, 1)
void eq_main(const float* __restrict__ xs, const float* __restrict__ xr,
             const int* __restrict__ ei, const float* __restrict__ dist,
             const float* __restrict__ rot,
             const float* __restrict__ W1, const float* __restrict__ b1,
             const float* __restrict__ W2, const float* __restrict__ b2,
             float* __restrict__ outS, float* __restrict__ outR,
             int E, int n_tiles)
{
    extern __shared__ __align__(16) unsigned char dyn[];
    const uint32_t sb = s2u(dyn);
    __half* sXh = (__half*)(dyn + B_XH);
    __half* sXl = (__half*)(dyn + B_XL);
    __half* sW1 = (__half*)(dyn + B_W1);
    __half* sW2 = (__half*)(dyn + B_W2);
    __half* sHh = (__half*)(dyn + B_HH);
    __half* sHl = (__half*)(dyn + B_HL);
    int*   sDst = (int*)  (dyn + B_DST);

    const int tid = threadIdx.x, wid = tid >> 5, lane = tid & 31;
    const int mw = wid >> 2, nw = wid & 3;          // 4 x 4 warp grid
    const int lr = lane & 15, lc = (lane >> 4) << 3;
    const int g  = lane >> 2, tc = (lane & 3) * 2;

    // ---- stage weights once (fp16) ----
    for (int i = tid; i < 256 * 128; i += NTHR) {
        int k = i >> 7, n = i & 127;
        sW1[k * W1STR + n] = __float2half_rn(W1[i]);
    }
    for (int i = tid; i < 128 * 96; i += NTHR) {
        int k = i / 96, n = i - k * 96;
        sW2[k * W2STR + n] = __float2half_rn(W2[i]);
    }
    __syncthreads();

    for (int t = blockIdx.x; t < n_tiles; t += gridDim.x) {
        const int base = t * ET;

        // ================= Phase A: gather + inverse rotate -> X hi/lo =================
        {
            const int eL = tid >> 2, s = tid & 3;
            const int e  = base + eL;
            const int ec = (e < E) ? e : (E - 1);
            const int srcn = ei[ec], dstn = ei[E + ec];
            if (s == 0) sDst[eL] = dstn;
            float4 rk[4];
            #pragma unroll
            for (int k = 0; k < 4; k++) rk[k] = *(const float4*)(rot + (size_t)ec * 16 + k * 4);
            const int rb = eL * XSTR;
            float tmp[8];
            // scalars
            #pragma unroll
            for (int q = 0; q < 2; q++) *(float4*)(tmp + 4*q) = *(const float4*)(xs + (size_t)dstn * 32 + s * 8 + 4*q);
            wr8(sXh, sXl, rb + s * 8, tmp);
            #pragma unroll
            for (int q = 0; q < 2; q++) *(float4*)(tmp + 4*q) = *(const float4*)(xs + (size_t)srcn * 32 + s * 8 + 4*q);
            wr8(sXh, sXl, rb + 96 + s * 8, tmp);
            // rotated reps
            #pragma unroll
            for (int jj = 0; jj < 2; jj++) {
                const int j = 2 * s + jj;
                float in[8];
                *(float4*)(in)     = *(const float4*)(xr + (size_t)dstn * 64 + j * 8);
                *(float4*)(in + 4) = *(const float4*)(xr + (size_t)dstn * 64 + j * 8 + 4);
                rot8(in, rk, tmp);  wr8(sXh, sXl, rb + 32 + j * 8, tmp);
                *(float4*)(in)     = *(const float4*)(xr + (size_t)srcn * 64 + j * 8);
                *(float4*)(in + 4) = *(const float4*)(xr + (size_t)srcn * 64 + j * 8 + 4);
                rot8(in, rk, tmp);  wr8(sXh, sXl, rb + 128 + j * 8, tmp);
            }
            // distance embedding
            #pragma unroll
            for (int q = 0; q < 2; q++) *(float4*)(tmp + 4*q) = *(const float4*)(dist + (size_t)ec * 64 + s * 16 + 4*q);
            wr8(sXh, sXl, rb + 192 + s * 16, tmp);
            #pragma unroll
            for (int q = 0; q < 2; q++) *(float4*)(tmp + 4*q) = *(const float4*)(dist + (size_t)ec * 64 + s * 16 + 8 + 4*q);
            wr8(sXh, sXl, rb + 200 + s * 16, tmp);
        }
        __syncthreads();

        // ================= GEMM1: 128 x 128 x 256, 2-pass (Xh,Xl) x W1 =================
        float acc[2][4][4] = {};
        {
            const uint32_t xhB = sb + B_XH, xlB = sb + B_XL, w1B = sb + B_W1;
            #pragma unroll 2
            for (int ks = 0; ks < 16; ks++) {
                const int k0 = ks * 16;
                uint32_t b[4][2];
                ldsm4t(w1B + (uint32_t)(((k0 + lr) * W1STR + nw * 32 + lc) * 2),
                       b[0][0], b[0][1], b[1][0], b[1][1]);
                ldsm4t(w1B + (uint32_t)(((k0 + lr) * W1STR + nw * 32 + 16 + lc) * 2),
                       b[2][0], b[2][1], b[3][0], b[3][1]);
                #pragma unroll
                for (int pass = 0; pass < 2; pass++) {
                    const uint32_t xb = pass ? xlB : xhB;
                    uint32_t A[2][4];
                    #pragma unroll
                    for (int mi = 0; mi < 2; mi++)
                        ldsm4(xb + (uint32_t)(((mw * 32 + mi * 16 + lr) * XSTR + k0 + lc) * 2),
                              A[mi][0], A[mi][1], A[mi][2], A[mi][3]);
                    #pragma unroll
                    for (int mi = 0; mi < 2; mi++)
                        #pragma unroll
                        for (int nt = 0; nt < 4; nt++)
                            mma16816(acc[mi][nt], A[mi], b[nt]);
                }
            }
        }
        __syncthreads();

        // ================= epilogue1: bias + silu -> H hi/lo =================
        #pragma unroll
        for (int mi = 0; mi < 2; mi++) {
            const int r0 = mw * 32 + mi * 16 + g;
            #pragma unroll
            for (int ni = 0; ni < 4; ni++) {
                const int c = nw * 32 + ni * 8 + tc;
                float2 bb = *(const float2*)(b1 + c);
                float v[4];
                v[0] = acc[mi][ni][0] + bb.x;  v[1] = acc[mi][ni][1] + bb.y;
                v[2] = acc[mi][ni][2] + bb.x;  v[3] = acc[mi][ni][3] + bb.y;
                #pragma unroll
                for (int q = 0; q < 4; q++) v[q] = v[q] / (1.f + __expf(-v[q]));
                #pragma unroll
                for (int rh = 0; rh < 2; rh++) {
                    const int r = r0 + rh * 8;
                    __half h0 = __float2half_rn(v[rh*2]), h1 = __float2half_rn(v[rh*2+1]);
                    __half l0 = __float2half_rn(v[rh*2]   - __half2float(h0));
                    __half l1 = __float2half_rn(v[rh*2+1] - __half2float(h1));
                    *(uint32_t*)(sHh + r * HSTR + c) = (uint32_t)__half_as_ushort(h0) | ((uint32_t)__half_as_ushort(h1) << 16);
                    *(uint32_t*)(sHl + r * HSTR + c) = (uint32_t)__half_as_ushort(l0) | ((uint32_t)__half_as_ushort(l1) << 16);
                }
            }
        }
        __syncthreads();

        // ================= GEMM2: 128 x 96 x 128, 2-pass (Hh,Hl) x W2 =================
        float acc2[2][3][4] = {};
        {
            const uint32_t hhB = sb + B_HH, hlB = sb + B_HL, w2B = sb + B_W2;
            #pragma unroll 2
            for (int ks = 0; ks < 8; ks++) {
                const int k0 = ks * 16;
                uint32_t b[3][2];
                ldsm4t(w2B + (uint32_t)(((k0 + lr) * W2STR + nw * 24 + lc) * 2),
                       b[0][0], b[0][1], b[1][0], b[1][1]);
                ldsm2t(w2B + (uint32_t)(((k0 + lr) * W2STR + nw * 24 + 16) * 2),
                       b[2][0], b[2][1]);
                #pragma unroll
                for (int pass = 0; pass < 2; pass++) {
                    const uint32_t hb = pass ? hlB : hhB;
                    uint32_t A[2][4];
                    #pragma unroll
                    for (int mi = 0; mi < 2; mi++)
                        ldsm4(hb + (uint32_t)(((mw * 32 + mi * 16 + lr) * HSTR + k0 + lc) * 2),
                              A[mi][0], A[mi][1], A[mi][2], A[mi][3]);
                    #pragma unroll
                    for (int mi = 0; mi < 2; mi++)
                        #pragma unroll
                        for (int nt = 0; nt < 3; nt++)
                            mma16816(acc2[mi][nt], A[mi], b[nt]);
                }
            }
        }

        // ================= epilogue2: bias + forward rotate + scatter =================
        #pragma unroll
        for (int mi = 0; mi < 2; mi++) {
            const int rr = mw * 32 + mi * 16 + g;
            #pragma unroll
            for (int rh = 0; rh < 2; rh++) {
                const int r = rr + rh * 8;
                const int e = base + r;
                if (e < E) {
                    const int nidx = sDst[r];
                    #pragma unroll
                    for (int ni = 0; ni < 3; ni++) {
                        const int c = nw * 24 + ni * 8 + tc;
                        float2 bb = *(const float2*)(b2 + c);
                        float m0 = acc2[mi][ni][rh*2]   + bb.x;
                        float m1 = acc2[mi][ni][rh*2+1] + bb.y;
                        if (c < 32) {
                            red2(outS + (size_t)nidx * 32 + c, m0, m1);
                        } else {
                            const int p = (c - 32) >> 1;
                            const int k = p & 3;
                            float4 R = *(const float4*)(rot + (size_t)e * 16 + k * 4);
                            red2(outR + (size_t)nidx * 64 + 2 * p,
                                 m0 * R.x + m1 * R.z, m0 * R.y + m1 * R.w);
                        }
                    }
                }
            }
        }
        __syncthreads();   // X/H area reused next tile
    }
}

extern "C" void kernel_launch(void* const* d_in, const int* in_sizes, int n_in,
                              void* d_out, int out_size)
{
    const float* xs   = (const float*)d_in[0];
    const float* xr   = (const float*)d_in[1];
    const int*   ei   = (const int*)  d_in[2];
    const float* dist = (const float*)d_in[3];
    const float* rot  = (const float*)d_in[4];
    const float* W1   = (const float*)d_in[5];
    const float* b1   = (const float*)d_in[6];
    const float* W2   = (const float*)d_in[7];
    const float* b2   = (const float*)d_in[8];

    const int N = in_sizes[0] / 32;
    const int E = in_sizes[2] / 2;
    const int n_tiles = (E + ET - 1) / ET;

    float* outS = (float*)d_out;
    float* outR = outS + (size_t)N * 32;

    cudaMemsetAsync(d_out, 0, (size_t)out_size * sizeof(float), 0);
    cudaFuncSetAttribute(eq_main, cudaFuncAttributeMaxDynamicSharedMemorySize, SMEMB);
    int grid = n_tiles < 148 ? n_tiles : 148;
    eq_main<<<grid, NTHR, SMEMB>>>(xs, xr, ei, dist, rot, W1, b1, W2, b2,
                                   outS, outR, E, n_tiles);
}

// round 6
// speedup vs baseline: 2.8925x; 1.2968x over previous
#include <cuda_runtime.h>
#include <cuda_fp16.h>
#include <cstdint>

#define NTHR  512
#define ET    128
#define XSTR  264     // halves (row stride, x8 for 16B-aligned ldsm rows)
#define W1STR 136
#define W2STR 96
#define HSTR  136
// byte offsets in dynamic smem
#define B_X0  0            // 67584
#define B_X1  67584        // 67584
#define B_W1  135168       // 69632
#define B_W2  204800       // 24576
#define B_DST 229376       // 2 * 128 * 4
#define SMEMB 230400

__device__ __forceinline__ uint32_t s2u(const void* p) {
    uint32_t a; asm("{ .reg .u64 t; cvta.to.shared.u64 t, %1; cvt.u32.u64 %0, t; }" : "=r"(a) : "l"(p)); return a;
}
__device__ __forceinline__ void ldsm4(uint32_t a, uint32_t& r0, uint32_t& r1, uint32_t& r2, uint32_t& r3) {
    asm volatile("ldmatrix.sync.aligned.m8n8.x4.shared.b16 {%0,%1,%2,%3}, [%4];"
                 : "=r"(r0), "=r"(r1), "=r"(r2), "=r"(r3) : "r"(a));
}
__device__ __forceinline__ void ldsm4t(uint32_t a, uint32_t& r0, uint32_t& r1, uint32_t& r2, uint32_t& r3) {
    asm volatile("ldmatrix.sync.aligned.m8n8.x4.trans.shared.b16 {%0,%1,%2,%3}, [%4];"
                 : "=r"(r0), "=r"(r1), "=r"(r2), "=r"(r3) : "r"(a));
}
__device__ __forceinline__ void ldsm2t(uint32_t a, uint32_t& r0, uint32_t& r1) {
    asm volatile("ldmatrix.sync.aligned.m8n8.x2.trans.shared.b16 {%0,%1}, [%2];"
                 : "=r"(r0), "=r"(r1) : "r"(a));
}
__device__ __forceinline__ void mma16816(float* c, const uint32_t* a, const uint32_t* b) {
    asm volatile("mma.sync.aligned.m16n8k16.row.col.f32.f16.f16.f32 "
                 "{%0,%1,%2,%3}, {%4,%5,%6,%7}, {%8,%9}, {%0,%1,%2,%3};"
                 : "+f"(c[0]), "+f"(c[1]), "+f"(c[2]), "+f"(c[3])
                 : "r"(a[0]), "r"(a[1]), "r"(a[2]), "r"(a[3]), "r"(b[0]), "r"(b[1]));
}
__device__ __forceinline__ void red2(float* p, float a, float b) {
    asm volatile("red.global.add.v2.f32 [%0], {%1,%2};" :: "l"(p), "f"(a), "f"(b) : "memory");
}
// 8 fp32 -> 8 fp16, one 16B STS at half-index idx (idx multiple of 8)
__device__ __forceinline__ void wr8h(__half* px, int idx, const float* v) {
    uint4 u;
    uint32_t* w = (uint32_t*)&u;
    #pragma unroll
    for (int q = 0; q < 4; q++) {
        __half h0 = __float2half_rn(v[2*q]), h1 = __float2half_rn(v[2*q+1]);
        w[q] = (uint32_t)__half_as_ushort(h0) | ((uint32_t)__half_as_ushort(h1) << 16);
    }
    *(uint4*)(px + idx) = u;
}
// inverse-rotate one rep (8 values)
__device__ __forceinline__ void rot8(const float* p, const float4* rk, float* o) {
    #pragma unroll
    for (int k = 0; k < 4; k++) {
        float x0 = p[2*k], x1 = p[2*k+1];
        o[2*k]   = x0 * rk[k].x + x1 * rk[k].y;
        o[2*k+1] = x0 * rk[k].z + x1 * rk[k].w;
    }
}

__global__ __launch_bounds__(NTHR, 1)
void eq_main(const float* __restrict__ xs, const float* __restrict__ xr,
             const int* __restrict__ ei, const float* __restrict__ dist,
             const float* __restrict__ rot,
             const float* __restrict__ W1, const float* __restrict__ b1,
             const float* __restrict__ W2, const float* __restrict__ b2,
             float* __restrict__ outS, float* __restrict__ outR,
             int E, int n_tiles)
{
    extern __shared__ __align__(16) unsigned char dyn[];
    const uint32_t sb = s2u(dyn);
    __half* sW1 = (__half*)(dyn + B_W1);
    __half* sW2 = (__half*)(dyn + B_W2);
    int*   sDst = (int*)  (dyn + B_DST);

    const int tid = threadIdx.x, lane = tid & 31, wid = tid >> 5;
    const int mw = wid >> 2, nw = wid & 3;
    const int lr = lane & 15, lc = (lane >> 4) << 3;
    const int g  = lane >> 2, tc = (lane & 3) * 2;

    // ---- stage weights once (fp16) ----
    for (int i = tid; i < 256 * 128; i += NTHR) {
        int k = i >> 7, n = i & 127;
        sW1[k * W1STR + n] = __float2half_rn(W1[i]);
    }
    for (int i = tid; i < 128 * 96; i += NTHR) {
        int k = i / 96, n = i - k * 96;
        sW2[k * W2STR + n] = __float2half_rn(W2[i]);
    }

    // phase-A gather/rotate for tile `t` into buffer `buf`
    auto phaseA = [&](int t, int buf) {
        __half* X = (__half*)(dyn + (buf ? B_X1 : B_X0));
        const int eL = tid >> 2, s = tid & 3;
        const int base = t * ET;
        const int e  = base + eL;
        const int ec = (e < E) ? e : (E - 1);
        const int srcn = ei[ec], dstn = ei[E + ec];
        if (s == 0) sDst[buf * ET + eL] = dstn;
        float4 rk[4];
        #pragma unroll
        for (int k = 0; k < 4; k++) rk[k] = *(const float4*)(rot + (size_t)ec * 16 + k * 4);
        const int rb = eL * XSTR;
        float tmp[8];
        #pragma unroll
        for (int q = 0; q < 2; q++) *(float4*)(tmp + 4*q) = *(const float4*)(xs + (size_t)dstn * 32 + s * 8 + 4*q);
        wr8h(X, rb + s * 8, tmp);
        #pragma unroll
        for (int q = 0; q < 2; q++) *(float4*)(tmp + 4*q) = *(const float4*)(xs + (size_t)srcn * 32 + s * 8 + 4*q);
        wr8h(X, rb + 96 + s * 8, tmp);
        #pragma unroll
        for (int jj = 0; jj < 2; jj++) {
            const int j = 2 * s + jj;
            float in[8];
            *(float4*)(in)     = *(const float4*)(xr + (size_t)dstn * 64 + j * 8);
            *(float4*)(in + 4) = *(const float4*)(xr + (size_t)dstn * 64 + j * 8 + 4);
            rot8(in, rk, tmp);  wr8h(X, rb + 32 + j * 8, tmp);
            *(float4*)(in)     = *(const float4*)(xr + (size_t)srcn * 64 + j * 8);
            *(float4*)(in + 4) = *(const float4*)(xr + (size_t)srcn * 64 + j * 8 + 4);
            rot8(in, rk, tmp);  wr8h(X, rb + 128 + j * 8, tmp);
        }
        #pragma unroll
        for (int q = 0; q < 2; q++) *(float4*)(tmp + 4*q) = *(const float4*)(dist + (size_t)ec * 64 + s * 16 + 4*q);
        wr8h(X, rb + 192 + s * 16, tmp);
        #pragma unroll
        for (int q = 0; q < 2; q++) *(float4*)(tmp + 4*q) = *(const float4*)(dist + (size_t)ec * 64 + s * 16 + 8 + 4*q);
        wr8h(X, rb + 200 + s * 16, tmp);
    };

    const int t0 = blockIdx.x, gstride = gridDim.x;
    if (t0 < n_tiles) phaseA(t0, 0);
    __syncthreads();

    int cur = 0;
    for (int t = t0; t < n_tiles; t += gstride) {
        const int base = t * ET;
        const uint32_t xB = sb + (cur ? B_X1 : B_X0);
        const uint32_t w1B = sb + B_W1, w2B = sb + B_W2;

        // ================= GEMM1: 128 x 128 x 256 =================
        float acc[2][4][4] = {};
        #pragma unroll 2
        for (int ks = 0; ks < 16; ks++) {
            const int k0 = ks * 16;
            uint32_t b[4][2];
            ldsm4t(w1B + (uint32_t)(((k0 + lr) * W1STR + nw * 32 + lc) * 2),
                   b[0][0], b[0][1], b[1][0], b[1][1]);
            ldsm4t(w1B + (uint32_t)(((k0 + lr) * W1STR + nw * 32 + 16 + lc) * 2),
                   b[2][0], b[2][1], b[3][0], b[3][1]);
            uint32_t A[2][4];
            #pragma unroll
            for (int mi = 0; mi < 2; mi++)
                ldsm4(xB + (uint32_t)(((mw * 32 + mi * 16 + lr) * XSTR + k0 + lc) * 2),
                      A[mi][0], A[mi][1], A[mi][2], A[mi][3]);
            #pragma unroll
            for (int mi = 0; mi < 2; mi++)
                #pragma unroll
                for (int nt = 0; nt < 4; nt++)
                    mma16816(acc[mi][nt], A[mi], b[nt]);
        }
        __syncthreads();   // all GEMM1 reads done before H overwrites X

        // ================= epilogue1: bias + silu -> H (overlays X[cur]) ==========
        {
            __half* sH = (__half*)(dyn + (cur ? B_X1 : B_X0));
            #pragma unroll
            for (int mi = 0; mi < 2; mi++) {
                const int r0 = mw * 32 + mi * 16 + g;
                #pragma unroll
                for (int ni = 0; ni < 4; ni++) {
                    const int c = nw * 32 + ni * 8 + tc;
                    float2 bb = *(const float2*)(b1 + c);
                    float v[4];
                    v[0] = acc[mi][ni][0] + bb.x;  v[1] = acc[mi][ni][1] + bb.y;
                    v[2] = acc[mi][ni][2] + bb.x;  v[3] = acc[mi][ni][3] + bb.y;
                    #pragma unroll
                    for (int q = 0; q < 4; q++) v[q] = v[q] / (1.f + __expf(-v[q]));
                    #pragma unroll
                    for (int rh = 0; rh < 2; rh++) {
                        const int r = r0 + rh * 8;
                        __half h0 = __float2half_rn(v[rh*2]), h1 = __float2half_rn(v[rh*2+1]);
                        *(uint32_t*)(sH + r * HSTR + c) =
                            (uint32_t)__half_as_ushort(h0) | ((uint32_t)__half_as_ushort(h1) << 16);
                    }
                }
            }
        }

        // ---- prefetch next tile's X into the other buffer (overlaps GEMM2) ----
        if (t + gstride < n_tiles) phaseA(t + gstride, cur ^ 1);
        __syncthreads();   // H visible; next X fully staged

        // ================= GEMM2: 128 x 96 x 128 =================
        float acc2[2][3][4] = {};
        {
            const uint32_t hB = xB;   // H overlays X[cur]
            #pragma unroll 2
            for (int ks = 0; ks < 8; ks++) {
                const int k0 = ks * 16;
                uint32_t b[3][2];
                ldsm4t(w2B + (uint32_t)(((k0 + lr) * W2STR + nw * 24 + lc) * 2),
                       b[0][0], b[0][1], b[1][0], b[1][1]);
                ldsm2t(w2B + (uint32_t)(((k0 + lr) * W2STR + nw * 24 + 16) * 2),
                       b[2][0], b[2][1]);
                uint32_t A[2][4];
                #pragma unroll
                for (int mi = 0; mi < 2; mi++)
                    ldsm4(hB + (uint32_t)(((mw * 32 + mi * 16 + lr) * HSTR + k0 + lc) * 2),
                          A[mi][0], A[mi][1], A[mi][2], A[mi][3]);
                #pragma unroll
                for (int mi = 0; mi < 2; mi++)
                    #pragma unroll
                    for (int nt = 0; nt < 3; nt++)
                        mma16816(acc2[mi][nt], A[mi], b[nt]);
            }
        }

        // ================= epilogue2: bias + forward rotate + scatter ============
        #pragma unroll
        for (int mi = 0; mi < 2; mi++) {
            const int rr = mw * 32 + mi * 16 + g;
            #pragma unroll
            for (int rh = 0; rh < 2; rh++) {
                const int r = rr + rh * 8;
                const int e = base + r;
                if (e < E) {
                    const int nidx = sDst[cur * ET + r];
                    #pragma unroll
                    for (int ni = 0; ni < 3; ni++) {
                        const int c = nw * 24 + ni * 8 + tc;
                        float2 bb = *(const float2*)(b2 + c);
                        float m0 = acc2[mi][ni][rh*2]   + bb.x;
                        float m1 = acc2[mi][ni][rh*2+1] + bb.y;
                        if (c < 32) {
                            red2(outS + (size_t)nidx * 32 + c, m0, m1);
                        } else {
                            const int p = (c - 32) >> 1;
                            const int k = p & 3;
                            float4 R = *(const float4*)(rot + (size_t)e * 16 + k * 4);
                            red2(outR + (size_t)nidx * 64 + 2 * p,
                                 m0 * R.x + m1 * R.z, m0 * R.y + m1 * R.w);
                        }
                    }
                }
            }
        }
        cur ^= 1;
        // no extra sync needed: next GEMM1 reads the buffer phaseA just filled
        // (ordered by the sync above), and the next writer of *this* buffer
        // runs only after the next iteration's post-GEMM1 sync.
    }
}

extern "C" void kernel_launch(void* const* d_in, const int* in_sizes, int n_in,
                              void* d_out, int out_size)
{
    const float* xs   = (const float*)d_in[0];
    const float* xr   = (const float*)d_in[1];
    const int*   ei   = (const int*)  d_in[2];
    const float* dist = (const float*)d_in[3];
    const float* rot  = (const float*)d_in[4];
    const float* W1   = (const float*)d_in[5];
    const float* b1   = (const float*)d_in[6];
    const float* W2   = (const float*)d_in[7];
    const float* b2   = (const float*)d_in[8];

    const int N = in_sizes[0] / 32;
    const int E = in_sizes[2] / 2;
    const int n_tiles = (E + ET - 1) / ET;

    float* outS = (float*)d_out;
    float* outR = outS + (size_t)N * 32;

    cudaMemsetAsync(d_out, 0, (size_t)out_size * sizeof(float), 0);
    cudaFuncSetAttribute(eq_main, cudaFuncAttributeMaxDynamicSharedMemorySize, SMEMB);
    int grid = n_tiles < 148 ? n_tiles : 148;
    eq_main<<<grid, NTHR, SMEMB>>>(xs, xr, ei, dist, rot, W1, b1, W2, b2,
                                   outS, outR, E, n_tiles);
}